// round 4
// baseline (speedup 1.0000x reference)
#include <cuda_runtime.h>

#define B_   8
#define NV_  2048
#define NF_  512
#define G_   96
#define VOX_ (G_*G_*G_)   // 884736

// ---------------- scratch (no allocation allowed) ----------------
static __device__ float4 g_box_raw[B_*NF_];      // xmin,xmax,ymin,ymax
static __device__ float2 g_zr_raw [B_*NF_];      // zmin,zmax
static __device__ float4 g_pl_raw [B_*NF_*3];    // 3 x (nx,ny,nz,c)
static __device__ float  g_key    [B_*NF_];
static __device__ float4 g_box    [B_*NF_];
static __device__ float2 g_zr     [B_*NF_];
static __device__ float4 g_pl     [B_*NF_*3];
static __device__ int    g_ntet   [B_];
static __device__ int    g_is32;

// ---------------- 0) facet dtype sniff (int64 vs silently-demoted int32) ----
// Valid indices are < 2048. Reading the buffer as u64 words: if the data is
// really int32, a word is lo | hi<<32 with hi an actual index; any word
// >= 2048 proves int32 packing. If the data is int64, every word < 2048.
__global__ void detect_k(const unsigned long long* __restrict__ f) {
    int any = 0;
    for (int idx = threadIdx.x; idx < B_*NF_*2; idx += blockDim.x)
        if (f[idx] >= (unsigned long long)NV_) any = 1;
    any = __syncthreads_or(any);
    if (threadIdx.x == 0) g_is32 = any;
}

// ---------------- 1) per-tet precompute ----------------
__global__ void prep_k(const float* __restrict__ verts, const void* __restrict__ fac) {
    int t = blockIdx.x * blockDim.x + threadIdx.x;
    if (t >= B_*NF_) return;
    int b = t >> 9;

    int i0, i1, i2, i3;
    if (g_is32) {
        const int* p = (const int*)fac + t*4;
        i0 = p[0]; i1 = p[1]; i2 = p[2]; i3 = p[3];
    } else {
        const long long* p = (const long long*)fac + t*4;
        i0 = (int)p[0]; i1 = (int)p[1]; i2 = (int)p[2]; i3 = (int)p[3];
    }

    const float* vb = verts + b * (NV_*3);
    float x0 = vb[3*i0+0], y0 = vb[3*i0+1], z0 = vb[3*i0+2];
    float x1 = vb[3*i1+0], y1 = vb[3*i1+1], z1 = vb[3*i1+2];
    float x2 = vb[3*i2+0], y2 = vb[3*i2+1], z2 = vb[3*i2+2];
    float x3 = vb[3*i3+0], y3 = vb[3*i3+1], z3 = vb[3*i3+2];

    // columns of M are edge vectors (matches reference T layout)
    float ca = x0-x3, cb = x1-x3, cc = x2-x3;
    float cd = y0-y3, ce = y1-y3, cf = y2-y3;
    float cg = z0-z3, ch = z1-z3, ci = z2-z3;

    // adjugate + det: multiply/sub kept uncontracted to mirror the reference
    float a00 = __fsub_rn(__fmul_rn(ce,ci), __fmul_rn(cf,ch));
    float a01 = __fsub_rn(__fmul_rn(cc,ch), __fmul_rn(cb,ci));
    float a02 = __fsub_rn(__fmul_rn(cb,cf), __fmul_rn(cc,ce));
    float a10 = __fsub_rn(__fmul_rn(cf,cg), __fmul_rn(cd,ci));
    float a11 = __fsub_rn(__fmul_rn(ca,ci), __fmul_rn(cc,cg));
    float a12 = __fsub_rn(__fmul_rn(cc,cd), __fmul_rn(ca,cf));
    float a20 = __fsub_rn(__fmul_rn(cd,ch), __fmul_rn(ce,cg));
    float a21 = __fsub_rn(__fmul_rn(cb,cg), __fmul_rn(ca,ch));
    float a22 = __fsub_rn(__fmul_rn(ca,ce), __fmul_rn(cb,cd));
    float u   = __fsub_rn(__fmul_rn(cd,ci), __fmul_rn(cf,cg));
    float det = __fadd_rn(__fsub_rn(__fmul_rn(ca,a00), __fmul_rn(cb,u)),
                          __fmul_rn(cc,a20));

    // fold 1/det and -adj*v3/det in double (<= 1 ulp vs dot/det)
    double inv = 1.0 / (double)det;
    float4 p0, p1, p2;
    p0.x = (float)((double)a00*inv); p0.y = (float)((double)a01*inv); p0.z = (float)((double)a02*inv);
    p1.x = (float)((double)a10*inv); p1.y = (float)((double)a11*inv); p1.z = (float)((double)a12*inv);
    p2.x = (float)((double)a20*inv); p2.y = (float)((double)a21*inv); p2.z = (float)((double)a22*inv);
    p0.w = (float)(-((double)a00*x3 + (double)a01*y3 + (double)a02*z3) * inv);
    p1.w = (float)(-((double)a10*x3 + (double)a11*y3 + (double)a12*z3) * inv);
    p2.w = (float)(-((double)a20*x3 + (double)a21*y3 + (double)a22*z3) * inv);

    const float M = 1e-5f;   // conservative AABB margin (filter-only, safe)
    float4 box;
    box.x = fminf(fminf(x0,x1), fminf(x2,x3)) - M;
    box.y = fmaxf(fmaxf(x0,x1), fmaxf(x2,x3)) + M;
    box.z = fminf(fminf(y0,y1), fminf(y2,y3)) - M;
    box.w = fmaxf(fmaxf(y0,y1), fmaxf(y2,y3)) + M;
    float2 zr;
    zr.x  = fminf(fminf(z0,z1), fminf(z2,z3)) - M;
    zr.y  = fmaxf(fmaxf(z0,z1), fmaxf(z2,z3)) + M;

    g_box_raw[t]   = box;
    g_zr_raw [t]   = zr;
    g_pl_raw [t*3+0] = p0;
    g_pl_raw [t*3+1] = p1;
    g_pl_raw [t*3+2] = p2;

    // degenerate (det==0 exactly) tets are provably inside==false -> drop
    float vol = fabsf(det);
    g_key[t] = (vol > 0.0f) ? vol : -1.0f;
}

// ---------------- 2) rank-sort by volume descending, drop degenerates ------
__global__ void sort_k() {
    int b = blockIdx.x, t = threadIdx.x;
    __shared__ float sk[NF_];
    float myk = g_key[b*NF_ + t];
    sk[t] = myk;
    __syncthreads();
    int rank = 0, nval = 0;
    #pragma unroll 8
    for (int j = 0; j < NF_; ++j) {
        float kj = sk[j];
        nval += (kj > 0.0f);
        rank += (kj > myk) || (kj == myk && j < t);
    }
    if (t == 0) g_ntet[b] = nval;
    int src = b*NF_ + t, dst = b*NF_ + rank;
    g_box[dst]     = g_box_raw[src];
    g_zr [dst]     = g_zr_raw [src];
    g_pl [dst*3+0] = g_pl_raw [src*3+0];
    g_pl [dst*3+1] = g_pl_raw [src*3+1];
    g_pl [dst*3+2] = g_pl_raw [src*3+2];
}

// ---------------- 3) main voxelize ----------------
// thread = one voxel; warp = 32 consecutive z (96 = 3*32 -> x,y warp-uniform)
__global__ __launch_bounds__(512) void vox_k(float* __restrict__ out) {
    __shared__ float4 s_box[NF_];
    __shared__ float2 s_zr [NF_];
    __shared__ float4 s_pl [NF_*3];

    int b = blockIdx.y;
    int ntet = g_ntet[b];
    for (int idx = threadIdx.x; idx < NF_; idx += 512) {
        s_box[idx] = g_box[b*NF_ + idx];
        s_zr [idx] = g_zr [b*NF_ + idx];
    }
    for (int idx = threadIdx.x; idx < NF_*3; idx += 512)
        s_pl[idx] = g_pl[b*NF_*3 + idx];
    __syncthreads();

    int vi = blockIdx.x * 512 + threadIdx.x;
    int z  = vi % G_;
    int r2 = vi / G_;
    int y  = r2 % G_;
    int x  = r2 / G_;

    float px = __fdiv_rn((float)(2*x - 95), 96.0f);
    float py = __fdiv_rn((float)(2*y - 95), 96.0f);
    float pz = __fdiv_rn((float)(2*z - 95), 96.0f);
    int zb = z & ~31;                        // warp-uniform z window
    float wzlo = __fdiv_rn((float)(2*zb        - 95), 96.0f);
    float wzhi = __fdiv_rn((float)(2*(zb + 31) - 95), 96.0f);

    bool found = false;
    for (int t = 0; t < ntet; ++t) {
        float4 bx = s_box[t];                // warp-uniform filter (convergent)
        if ((px < bx.x) | (px > bx.y) | (py < bx.z) | (py > bx.w)) continue;
        float2 bz = s_zr[t];
        if ((wzhi < bz.x) | (wzlo > bz.y)) continue;
        if (!found) {
            float4 p0 = s_pl[3*t + 0];
            float4 p1 = s_pl[3*t + 1];
            float4 p2 = s_pl[3*t + 2];
            float l0 = fmaf(p0.x, px, fmaf(p0.y, py, fmaf(p0.z, pz, p0.w)));
            float l1 = fmaf(p1.x, px, fmaf(p1.y, py, fmaf(p1.z, pz, p1.w)));
            float l2 = fmaf(p2.x, px, fmaf(p2.y, py, fmaf(p2.z, pz, p2.w)));
            float l3 = 1.0f - (l0 + l1 + l2);
            // equivalent to all lam in [0,1]; NaN/Inf (det==0 path) -> false
            found = (l0 >= 0.0f) & (l1 >= 0.0f) & (l2 >= 0.0f) & (l3 >= 0.0f);
        }
        if (__all_sync(0xffffffffu, found)) break;   // warp early exit
    }
    out[(size_t)b * VOX_ + vi] = found ? 1.0f : 0.0f;
}

// ---------------- launch ----------------
extern "C" void kernel_launch(void* const* d_in, const int* in_sizes, int n_in,
                              void* d_out, int out_size) {
    const float* verts = (const float*)d_in[0];
    const void*  fac   = d_in[1];
    (void)in_sizes; (void)n_in; (void)out_size;

    detect_k<<<1, 256>>>((const unsigned long long*)fac);
    prep_k<<<(B_*NF_ + 255) / 256, 256>>>(verts, fac);
    sort_k<<<B_, NF_>>>();
    vox_k<<<dim3(VOX_ / 512, B_), 512>>>((float*)d_out);
}

// round 7
// speedup vs baseline: 2.5413x; 2.5413x over previous
#include <cuda_runtime.h>

#define B_   8
#define NV_  2048
#define NF_  512
#define G_   96
#define VOX_ (G_*G_*G_)   // 884736

// ---------------- scratch (no allocation allowed) ----------------
static __device__ float4 g_pl_raw [B_*NF_*3];    // 3 x (nx,ny,nz,c)
static __device__ int4   g_ib_raw [B_*NF_];      // xlo,xhi,ylo,yhi
static __device__ int2   g_zb_raw [B_*NF_];      // zlo,zhi
static __device__ float  g_key    [B_*NF_];
static __device__ float4 g_pl     [B_*NF_*3];
static __device__ int4   g_ib     [B_*NF_];
static __device__ int2   g_zb     [B_*NF_];
static __device__ int    g_ntet   [B_];
static __device__ int    g_is32;

// ---------------- 0) output zero-fill ----------------
__global__ void zero_k(float4* __restrict__ o) {
    o[blockIdx.x * 256 + threadIdx.x] = make_float4(0.f, 0.f, 0.f, 0.f);
}

// ---------------- 1) facet dtype sniff (int64 vs silently-demoted int32) ---
__global__ void detect_k(const unsigned long long* __restrict__ f) {
    int any = 0;
    for (int idx = threadIdx.x; idx < B_*NF_*2; idx += blockDim.x)
        if (f[idx] >= (unsigned long long)NV_) any = 1;
    any = __syncthreads_or(any);
    if (threadIdx.x == 0) g_is32 = any;
}

// ---------------- 2) per-tet precompute ----------------
__global__ void prep_k(const float* __restrict__ verts, const void* __restrict__ fac) {
    int t = blockIdx.x * blockDim.x + threadIdx.x;
    if (t >= B_*NF_) return;
    int b = t >> 9;

    int i0, i1, i2, i3;
    if (g_is32) {
        const int* p = (const int*)fac + t*4;
        i0 = p[0]; i1 = p[1]; i2 = p[2]; i3 = p[3];
    } else {
        const long long* p = (const long long*)fac + t*4;
        i0 = (int)p[0]; i1 = (int)p[1]; i2 = (int)p[2]; i3 = (int)p[3];
    }

    const float* vb = verts + b * (NV_*3);
    float x0 = vb[3*i0+0], y0 = vb[3*i0+1], z0 = vb[3*i0+2];
    float x1 = vb[3*i1+0], y1 = vb[3*i1+1], z1 = vb[3*i1+2];
    float x2 = vb[3*i2+0], y2 = vb[3*i2+1], z2 = vb[3*i2+2];
    float x3 = vb[3*i3+0], y3 = vb[3*i3+1], z3 = vb[3*i3+2];

    float ca = x0-x3, cb = x1-x3, cc = x2-x3;
    float cd = y0-y3, ce = y1-y3, cf = y2-y3;
    float cg = z0-z3, ch = z1-z3, ci = z2-z3;

    float a00 = __fsub_rn(__fmul_rn(ce,ci), __fmul_rn(cf,ch));
    float a01 = __fsub_rn(__fmul_rn(cc,ch), __fmul_rn(cb,ci));
    float a02 = __fsub_rn(__fmul_rn(cb,cf), __fmul_rn(cc,ce));
    float a10 = __fsub_rn(__fmul_rn(cf,cg), __fmul_rn(cd,ci));
    float a11 = __fsub_rn(__fmul_rn(ca,ci), __fmul_rn(cc,cg));
    float a12 = __fsub_rn(__fmul_rn(cc,cd), __fmul_rn(ca,cf));
    float a20 = __fsub_rn(__fmul_rn(cd,ch), __fmul_rn(ce,cg));
    float a21 = __fsub_rn(__fmul_rn(cb,cg), __fmul_rn(ca,ch));
    float a22 = __fsub_rn(__fmul_rn(ca,ce), __fmul_rn(cb,cd));
    float u   = __fsub_rn(__fmul_rn(cd,ci), __fmul_rn(cf,cg));
    float det = __fadd_rn(__fsub_rn(__fmul_rn(ca,a00), __fmul_rn(cb,u)),
                          __fmul_rn(cc,a20));

    double inv = 1.0 / (double)det;
    float4 p0, p1, p2;
    p0.x = (float)((double)a00*inv); p0.y = (float)((double)a01*inv); p0.z = (float)((double)a02*inv);
    p1.x = (float)((double)a10*inv); p1.y = (float)((double)a11*inv); p1.z = (float)((double)a12*inv);
    p2.x = (float)((double)a20*inv); p2.y = (float)((double)a21*inv); p2.z = (float)((double)a22*inv);
    p0.w = (float)(-((double)a00*x3 + (double)a01*y3 + (double)a02*z3) * inv);
    p1.w = (float)(-((double)a10*x3 + (double)a11*y3 + (double)a12*z3) * inv);
    p2.w = (float)(-((double)a20*x3 + (double)a21*y3 + (double)a22*z3) * inv);

    const float M = 1e-5f;  // conservative AABB margin
    float bxmin = fminf(fminf(x0,x1), fminf(x2,x3)) - M;
    float bxmax = fmaxf(fmaxf(x0,x1), fmaxf(x2,x3)) + M;
    float bymin = fminf(fminf(y0,y1), fminf(y2,y3)) - M;
    float bymax = fmaxf(fmaxf(y0,y1), fmaxf(y2,y3)) + M;
    float bzmin = fminf(fminf(z0,z1), fminf(z2,z3)) - M;
    float bzmax = fmaxf(fmaxf(z0,z1), fmaxf(z2,z3)) + M;

    // voxel-center index range, +/-1 guard voxel for FP safety
    // center(i) = (2i-95)/96 >= v  <=>  i >= (96v+95)/2
    int4 ib; int2 zb;
    ib.x = max(0,  (int)ceilf ((96.f*bxmin + 95.f)*0.5f) - 1);
    ib.y = min(95, (int)floorf((96.f*bxmax + 95.f)*0.5f) + 1);
    ib.z = max(0,  (int)ceilf ((96.f*bymin + 95.f)*0.5f) - 1);
    ib.w = min(95, (int)floorf((96.f*bymax + 95.f)*0.5f) + 1);
    zb.x = max(0,  (int)ceilf ((96.f*bzmin + 95.f)*0.5f) - 1);
    zb.y = min(95, (int)floorf((96.f*bzmax + 95.f)*0.5f) + 1);

    g_pl_raw[t*3+0] = p0;
    g_pl_raw[t*3+1] = p1;
    g_pl_raw[t*3+2] = p2;
    g_ib_raw[t] = ib;
    g_zb_raw[t] = zb;

    // degenerate tets (det==0) are provably inside==false in the reference
    float vol = fabsf(det);
    long long nvox = (long long)(ib.y-ib.x+1) * (ib.w-ib.z+1) * (zb.y-zb.x+1);
    g_key[t] = (vol > 0.0f) ? (float)nvox : -1.0f;   // sort key: box voxel count
}

// ---------------- 3) rank-sort by box size desc, drop degenerates ----------
__global__ void sort_k() {
    int b = blockIdx.x, t = threadIdx.x;
    __shared__ float sk[NF_];
    float myk = g_key[b*NF_ + t];
    sk[t] = myk;
    __syncthreads();
    int rank = 0, nval = 0;
    #pragma unroll 8
    for (int j = 0; j < NF_; ++j) {
        float kj = sk[j];
        nval += (kj > 0.0f);
        rank += (kj > myk) || (kj == myk && j < t);
    }
    if (t == 0) g_ntet[b] = nval;
    int src = b*NF_ + t, dst = b*NF_ + rank;
    g_ib[dst]     = g_ib_raw[src];
    g_zb[dst]     = g_zb_raw[src];
    g_pl[dst*3+0] = g_pl_raw[src*3+0];
    g_pl[dst*3+1] = g_pl_raw[src*3+1];
    g_pl[dst*3+2] = g_pl_raw[src*3+2];
}

// ---------------- 4) per-tet scatter rasterization ----------------
// block = one tet; 8 warps stride y; lanes = 32 consecutive z; block loops x.
__global__ __launch_bounds__(256) void vox_k(float* __restrict__ out) {
    __shared__ float s_p[G_];          // voxel-center coordinate LUT
    int b = blockIdx.y;
    int t = blockIdx.x;
    if (threadIdx.x < G_)
        s_p[threadIdx.x] = __fdiv_rn((float)(2*(int)threadIdx.x - 95), 96.0f);
    __syncthreads();
    if (t >= g_ntet[b]) return;

    int idx = b*NF_ + t;
    int4  ib = g_ib[idx];
    int2  zb = g_zb[idx];
    float4 p0 = g_pl[idx*3+0];
    float4 p1 = g_pl[idx*3+1];
    float4 p2 = g_pl[idx*3+2];

    int warp = threadIdx.x >> 5, lane = threadIdx.x & 31;
    int nzc = ((zb.y - zb.x) >> 5) + 1;          // 1..3 z-chunks of 32

    float pzc[3];
    #pragma unroll
    for (int k = 0; k < 3; ++k) {
        int z = zb.x + k*32 + lane;
        pzc[k] = s_p[min(z, 95)];
    }

    float* outb = out + (size_t)b * VOX_;
    for (int xi = ib.x; xi <= ib.y; ++xi) {
        float px  = s_p[xi];
        float e0x = fmaf(p0.x, px, p0.w);
        float e1x = fmaf(p1.x, px, p1.w);
        float e2x = fmaf(p2.x, px, p2.w);
        int   rowx = xi * G_;
        for (int yi = ib.z + warp; yi <= ib.w; yi += 8) {
            float py = s_p[yi];
            float e0 = fmaf(p0.y, py, e0x);
            float e1 = fmaf(p1.y, py, e1x);
            float e2 = fmaf(p2.y, py, e2x);
            float* col = outb + (size_t)(rowx + yi) * G_ + zb.x + lane;
            #pragma unroll
            for (int k = 0; k < 3; ++k) {
                if (k >= nzc) break;
                float l0 = fmaf(p0.z, pzc[k], e0);
                float l1 = fmaf(p1.z, pzc[k], e1);
                float l2 = fmaf(p2.z, pzc[k], e2);
                float l3 = 1.0f - (l0 + l1 + l2);
                // NaN-safe: all-lam NaN (degenerate) -> m NaN -> false
                float m = fminf(fminf(l0, l1), fminf(l2, l3));
                int   z = zb.x + k*32 + lane;
                if ((m >= 0.0f) && (z <= zb.y)) col[k*32] = 1.0f;
            }
        }
    }
}

// ---------------- launch ----------------
extern "C" void kernel_launch(void* const* d_in, const int* in_sizes, int n_in,
                              void* d_out, int out_size) {
    const float* verts = (const float*)d_in[0];
    const void*  fac   = d_in[1];
    (void)in_sizes; (void)n_in; (void)out_size;

    zero_k  <<<(B_*VOX_/4) / 256, 256>>>((float4*)d_out);
    detect_k<<<1, 256>>>((const unsigned long long*)fac);
    prep_k  <<<(B_*NF_ + 255) / 256, 256>>>(verts, fac);
    sort_k  <<<B_, NF_>>>();
    vox_k   <<<dim3(NF_, B_), 256>>>((float*)d_out);
}

// round 8
// speedup vs baseline: 4.1675x; 1.6399x over previous
#include <cuda_runtime.h>

#define B_   8
#define NV_  2048
#define NF_  512
#define G_   96
#define VOX_ (G_*G_*G_)   // 884736

// ---------------- scratch (no allocation allowed) ----------------
struct Tet {
    float4 p0, p1, p2;   // plane r: (nx,ny,nz,c), lambda_r = nx*px+ny*py+nz*pz+c
    float4 w;            // per-plane -48/nz (x,y,z -> planes 0..2, w -> plane 3)
    int4   ib;           // xlo,xhi,ylo,yhi  (voxel index AABB, +1 guard)
    int2   zb;           // zlo,zhi
    int    flags;        // 0 = degenerate skip, 1 = fast path, 2 = fallback
    int    pad;
};
static __device__ Tet g_t[B_*NF_];
static __device__ int g_is32;

// ---------------- 0) output zero-fill ----------------
__global__ void zero_k(float4* __restrict__ o) {
    o[blockIdx.x * 256 + threadIdx.x] = make_float4(0.f, 0.f, 0.f, 0.f);
}

// ---------------- 1) facet dtype sniff (int64 vs silently-demoted int32) ---
__global__ void detect_k(const unsigned long long* __restrict__ f) {
    int any = 0;
    for (int idx = threadIdx.x; idx < B_*NF_*2; idx += blockDim.x)
        if (f[idx] >= (unsigned long long)NV_) any = 1;
    any = __syncthreads_or(any);
    if (threadIdx.x == 0) g_is32 = any;
}

// ---------------- 2) per-tet precompute ----------------
__device__ __forceinline__ bool ill_cond(float nx, float ny, float nz, float c) {
    float M = fmaxf(fmaxf(fabsf(nx), fabsf(ny)), fmaxf(fabsf(c), 1.0f));
    return 1e4f * fabsf(nz) < M;   // crossing-index error could exceed ~0.25 voxel
}

__global__ void prep_k(const float* __restrict__ verts, const void* __restrict__ fac) {
    int t = blockIdx.x * blockDim.x + threadIdx.x;
    if (t >= B_*NF_) return;
    int b = t >> 9;

    int i0, i1, i2, i3;
    if (g_is32) {
        const int* p = (const int*)fac + t*4;
        i0 = p[0]; i1 = p[1]; i2 = p[2]; i3 = p[3];
    } else {
        const long long* p = (const long long*)fac + t*4;
        i0 = (int)p[0]; i1 = (int)p[1]; i2 = (int)p[2]; i3 = (int)p[3];
    }

    const float* vb = verts + b * (NV_*3);
    float x0 = vb[3*i0+0], y0 = vb[3*i0+1], z0 = vb[3*i0+2];
    float x1 = vb[3*i1+0], y1 = vb[3*i1+1], z1 = vb[3*i1+2];
    float x2 = vb[3*i2+0], y2 = vb[3*i2+1], z2 = vb[3*i2+2];
    float x3 = vb[3*i3+0], y3 = vb[3*i3+1], z3 = vb[3*i3+2];

    float ca = x0-x3, cb = x1-x3, cc = x2-x3;
    float cd = y0-y3, ce = y1-y3, cf = y2-y3;
    float cg = z0-z3, ch = z1-z3, ci = z2-z3;

    // adjugate + det, uncontracted to mirror the reference
    float a00 = __fsub_rn(__fmul_rn(ce,ci), __fmul_rn(cf,ch));
    float a01 = __fsub_rn(__fmul_rn(cc,ch), __fmul_rn(cb,ci));
    float a02 = __fsub_rn(__fmul_rn(cb,cf), __fmul_rn(cc,ce));
    float a10 = __fsub_rn(__fmul_rn(cf,cg), __fmul_rn(cd,ci));
    float a11 = __fsub_rn(__fmul_rn(ca,ci), __fmul_rn(cc,cg));
    float a12 = __fsub_rn(__fmul_rn(cc,cd), __fmul_rn(ca,cf));
    float a20 = __fsub_rn(__fmul_rn(cd,ch), __fmul_rn(ce,cg));
    float a21 = __fsub_rn(__fmul_rn(cb,cg), __fmul_rn(ca,ch));
    float a22 = __fsub_rn(__fmul_rn(ca,ce), __fmul_rn(cb,cd));
    float u   = __fsub_rn(__fmul_rn(cd,ci), __fmul_rn(cf,cg));
    float det = __fadd_rn(__fsub_rn(__fmul_rn(ca,a00), __fmul_rn(cb,u)),
                          __fmul_rn(cc,a20));

    double inv = 1.0 / (double)det;
    float4 p0, p1, p2;
    p0.x = (float)((double)a00*inv); p0.y = (float)((double)a01*inv); p0.z = (float)((double)a02*inv);
    p1.x = (float)((double)a10*inv); p1.y = (float)((double)a11*inv); p1.z = (float)((double)a12*inv);
    p2.x = (float)((double)a20*inv); p2.y = (float)((double)a21*inv); p2.z = (float)((double)a22*inv);
    p0.w = (float)(-((double)a00*x3 + (double)a01*y3 + (double)a02*z3) * inv);
    p1.w = (float)(-((double)a10*x3 + (double)a11*y3 + (double)a12*z3) * inv);
    p2.w = (float)(-((double)a20*x3 + (double)a21*y3 + (double)a22*z3) * inv);

    // plane 3 (l3 = 1 - l0 - l1 - l2) linear-form coefficients (approx use only)
    float n3x = -(p0.x + p1.x + p2.x);
    float n3y = -(p0.y + p1.y + p2.y);
    float n3z = -(p0.z + p1.z + p2.z);
    float c3  = 1.0f - (p0.w + p1.w + p2.w);

    const float M = 1e-5f;  // conservative AABB margin
    float bxmin = fminf(fminf(x0,x1), fminf(x2,x3)) - M;
    float bxmax = fmaxf(fmaxf(x0,x1), fmaxf(x2,x3)) + M;
    float bymin = fminf(fminf(y0,y1), fminf(y2,y3)) - M;
    float bymax = fmaxf(fmaxf(y0,y1), fmaxf(y2,y3)) + M;
    float bzmin = fminf(fminf(z0,z1), fminf(z2,z3)) - M;
    float bzmax = fmaxf(fmaxf(z0,z1), fmaxf(z2,z3)) + M;

    Tet T;
    T.ib.x = max(0,  (int)ceilf ((96.f*bxmin + 95.f)*0.5f) - 1);
    T.ib.y = min(95, (int)floorf((96.f*bxmax + 95.f)*0.5f) + 1);
    T.ib.z = max(0,  (int)ceilf ((96.f*bymin + 95.f)*0.5f) - 1);
    T.ib.w = min(95, (int)floorf((96.f*bymax + 95.f)*0.5f) + 1);
    T.zb.x = max(0,  (int)ceilf ((96.f*bzmin + 95.f)*0.5f) - 1);
    T.zb.y = min(95, (int)floorf((96.f*bzmax + 95.f)*0.5f) + 1);

    int flags;
    if (!(fabsf(det) > 0.0f)) flags = 0;                 // degenerate -> never inside
    else if (ill_cond(p0.x,p0.y,p0.z,p0.w) || ill_cond(p1.x,p1.y,p1.z,p1.w) ||
             ill_cond(p2.x,p2.y,p2.z,p2.w) || ill_cond(n3x,n3y,n3z,c3))
        flags = 2;                                       // rare: exact chunked path
    else flags = 1;

    float4 w;
    w.x = (float)(-48.0 / (double)p0.z);
    w.y = (float)(-48.0 / (double)p1.z);
    w.z = (float)(-48.0 / (double)p2.z);
    w.w = (float)(-48.0 / (double)n3z);

    T.p0 = p0; T.p1 = p1; T.p2 = p2; T.w = w; T.flags = flags; T.pad = 0;
    g_t[t] = T;
}

// ---------------- 3) per-tet rasterize: exact z-run per column ------------
// block = one tet; 8 warps stride over (x, y-group) work units;
// phase 1/2: lanes = 32 y-columns;  phase 3: lanes = z (coalesced fill).
__global__ __launch_bounds__(256) void vox_k(float* __restrict__ out) {
    __shared__ float s_p[G_];
    if (threadIdx.x < G_)
        s_p[threadIdx.x] = __fdiv_rn((float)(2*(int)threadIdx.x - 95), 96.0f);
    __syncthreads();

    const Tet& T = g_t[blockIdx.y * NF_ + blockIdx.x];
    int flags = T.flags;
    if (flags == 0) return;

    int warp = threadIdx.x >> 5, lane = threadIdx.x & 31;
    float4 P0 = T.p0, P1 = T.p1, P2 = T.p2;
    int4 ib = T.ib; int2 zb = T.zb;
    float* outb = out + (size_t)blockIdx.y * VOX_;

    if (flags == 2) {
        // -------- fallback: exact chunked test over whole box (R4 path) -----
        int nzc = ((zb.y - zb.x) >> 5) + 1;
        float pzc[3];
        #pragma unroll
        for (int k = 0; k < 3; ++k)
            pzc[k] = s_p[min(zb.x + k*32 + lane, 95)];
        for (int xi = ib.x; xi <= ib.y; ++xi) {
            float px  = s_p[xi];
            float e0x = fmaf(P0.x, px, P0.w);
            float e1x = fmaf(P1.x, px, P1.w);
            float e2x = fmaf(P2.x, px, P2.w);
            int rowx = xi * G_;
            for (int yi = ib.z + warp; yi <= ib.w; yi += 8) {
                float py = s_p[yi];
                float e0 = fmaf(P0.y, py, e0x);
                float e1 = fmaf(P1.y, py, e1x);
                float e2 = fmaf(P2.y, py, e2x);
                float* col = outb + (size_t)(rowx + yi) * G_ + zb.x + lane;
                #pragma unroll
                for (int k = 0; k < 3; ++k) {
                    if (k >= nzc) break;
                    float l0 = fmaf(P0.z, pzc[k], e0);
                    float l1 = fmaf(P1.z, pzc[k], e1);
                    float l2 = fmaf(P2.z, pzc[k], e2);
                    float l3 = 1.0f - (l0 + l1 + l2);
                    float m = fminf(fminf(l0, l1), fminf(l2, l3));
                    int z = zb.x + k*32 + lane;
                    if ((m >= 0.0f) && (z <= zb.y)) col[k*32] = 1.0f;
                }
            }
        }
        return;
    }

    // -------- fast path --------
    float4 W = T.w;
    bool s0 = P0.z > 0.0f, s1 = P1.z > 0.0f, s2 = P2.z > 0.0f;
    bool s3 = (-(P0.z + P1.z + P2.z)) > 0.0f;   // sign of n3z

    int nx = ib.y - ib.x + 1;
    int ny = ib.w - ib.z + 1;
    int nyg = (ny + 31) >> 5;
    int total = nx * nyg;

    for (int g = warp; g < total; g += 8) {
        int gx = g / nyg;
        int xi = ib.x + gx;
        int ybase = ib.z + (g - gx*nyg) * 32;

        float px  = s_p[xi];
        float ex0 = fmaf(P0.x, px, P0.w);
        float ex1 = fmaf(P1.x, px, P1.w);
        float ex2 = fmaf(P2.x, px, P2.w);

        int  y   = ybase + lane;
        bool yok = (y <= ib.w);
        float py = s_p[y > 95 ? 95 : y];
        float e0 = fmaf(P0.y, py, ex0);
        float e1 = fmaf(P1.y, py, ex1);
        float e2 = fmaf(P2.y, py, ex2);
        float e3 = 1.0f - (e0 + e1 + e2);       // approx linear const, plane 3

        // approximate crossing positions in z-index space
        float i0 = fmaf(e0, W.x, 47.5f);
        float i1 = fmaf(e1, W.y, 47.5f);
        float i2 = fmaf(e2, W.z, 47.5f);
        float i3 = fmaf(e3, W.w, 47.5f);
        float lo = fmaxf(fmaxf(s0 ? i0 : -1e30f, s1 ? i1 : -1e30f),
                         fmaxf(s2 ? i2 : -1e30f, s3 ? i3 : -1e30f));
        float hi = fminf(fminf(s0 ? 1e30f : i0, s1 ? 1e30f : i1),
                         fminf(s2 ? 1e30f : i2, s3 ? 1e30f : i3));
        int sA = __float2int_ru(lo);
        int eA = __float2int_rd(hi);

        int st = 127, en = -1;
        bool act = yok && (sA <= eA + 2);       // crossing err < 0.25 => safe skip
        if (__any_sync(0xffffffffu, act)) {
            // exact membership test — IDENTICAL FP chain to the passing kernel
            auto TST = [&](int z) -> bool {
                float pz = s_p[z];
                float l0 = fmaf(P0.z, pz, e0);
                float l1 = fmaf(P1.z, pz, e1);
                float l2 = fmaf(P2.z, pz, e2);
                float l3 = 1.0f - (l0 + l1 + l2);
                return fminf(fminf(l0, l1), fminf(l2, l3)) >= 0.0f;
            };
            if (act) {
                // true start = first exact-true among {sA-1, sA, sA+1}
                int cs0 = min(max(sA-1, 0), 95);
                int cs1 = min(max(sA  , 0), 95);
                int cs2 = min(max(sA+1, 0), 95);
                bool t0 = TST(cs0), t1 = TST(cs1), t2 = TST(cs2);
                st = t0 ? cs0 : (t1 ? cs1 : (t2 ? cs2 : 127));
                // true end = first exact-true among {eA+1, eA, eA-1} (descending)
                int ce0 = min(max(eA+1, 0), 95);
                int ce1 = min(max(eA  , 0), 95);
                int ce2 = min(max(eA-1, 0), 95);
                bool u0 = TST(ce0), u1 = TST(ce1), u2 = TST(ce2);
                en = u0 ? ce0 : (u1 ? ce1 : (u2 ? ce2 : -1));
            }
        }

        // phase 3: coalesced fill, lanes = z, loop over nonempty columns
        unsigned mrun = __ballot_sync(0xffffffffu, st <= en);
        int pk = (st << 8) | (en & 255);
        while (mrun) {
            int j = __ffs(mrun) - 1; mrun &= mrun - 1;
            int pkj = __shfl_sync(0xffffffffu, pk, j);
            int bs = pkj >> 8, be = pkj & 255;
            float* col = outb + (size_t)(xi * G_ + ybase + j) * G_;
            for (int zz = bs + lane; zz <= be; zz += 32)
                col[zz] = 1.0f;
        }
    }
}

// ---------------- launch ----------------
extern "C" void kernel_launch(void* const* d_in, const int* in_sizes, int n_in,
                              void* d_out, int out_size) {
    const float* verts = (const float*)d_in[0];
    const void*  fac   = d_in[1];
    (void)in_sizes; (void)n_in; (void)out_size;

    zero_k  <<<(B_*VOX_/4) / 256, 256>>>((float4*)d_out);
    detect_k<<<1, 256>>>((const unsigned long long*)fac);
    prep_k  <<<(B_*NF_ + 255) / 256, 256>>>(verts, fac);
    vox_k   <<<dim3(NF_, B_), 256>>>((float*)d_out);
}

// round 9
// speedup vs baseline: 8.3468x; 2.0029x over previous
#include <cuda_runtime.h>

#define B_   8
#define NV_  2048
#define NF_  512
#define G_   96
#define VOX_ (G_*G_*G_)   // 884736

// ---------------- scratch (no allocation allowed) ----------------
struct Tet {
    float4 p0, p1, p2;   // plane r: (nx,ny,nz,c), lambda_r = nx*px+ny*py+nz*pz+c
    float4 w;            // per-plane -48/nz (x,y,z -> planes 0..2, w -> plane 3)
    int4   ib;           // xlo,xhi,ylo,yhi  (voxel index AABB, +1 guard)
    int2   zb;           // zlo,zhi
    int    flags;        // 0 = degenerate skip, 1 = fast path, 2 = fallback
    int    pad;
};
static __device__ Tet g_t[B_*NF_];
static __device__ int g_is32;

// ---------------- 0) output zero-fill ----------------
__global__ void zero_k(float4* __restrict__ o) {
    o[blockIdx.x * 256 + threadIdx.x] = make_float4(0.f, 0.f, 0.f, 0.f);
}

// ---------------- 1) facet dtype sniff (int64 vs silently-demoted int32) ---
__global__ void detect_k(const unsigned long long* __restrict__ f) {
    int any = 0;
    for (int idx = threadIdx.x; idx < B_*NF_*2; idx += blockDim.x)
        if (f[idx] >= (unsigned long long)NV_) any = 1;
    any = __syncthreads_or(any);
    if (threadIdx.x == 0) g_is32 = any;
}

// ---------------- 2) per-tet precompute ----------------
__device__ __forceinline__ bool ill_cond(float nx, float ny, float nz, float c) {
    float M = fmaxf(fmaxf(fabsf(nx), fabsf(ny)), fmaxf(fabsf(c), 1.0f));
    return 1e4f * fabsf(nz) < M;   // crossing-index error could exceed ~0.25 voxel
}

__global__ void prep_k(const float* __restrict__ verts, const void* __restrict__ fac) {
    int t = blockIdx.x * blockDim.x + threadIdx.x;
    if (t >= B_*NF_) return;
    int b = t >> 9;

    int i0, i1, i2, i3;
    if (g_is32) {
        const int* p = (const int*)fac + t*4;
        i0 = p[0]; i1 = p[1]; i2 = p[2]; i3 = p[3];
    } else {
        const long long* p = (const long long*)fac + t*4;
        i0 = (int)p[0]; i1 = (int)p[1]; i2 = (int)p[2]; i3 = (int)p[3];
    }

    const float* vb = verts + b * (NV_*3);
    float x0 = vb[3*i0+0], y0 = vb[3*i0+1], z0 = vb[3*i0+2];
    float x1 = vb[3*i1+0], y1 = vb[3*i1+1], z1 = vb[3*i1+2];
    float x2 = vb[3*i2+0], y2 = vb[3*i2+1], z2 = vb[3*i2+2];
    float x3 = vb[3*i3+0], y3 = vb[3*i3+1], z3 = vb[3*i3+2];

    float ca = x0-x3, cb = x1-x3, cc = x2-x3;
    float cd = y0-y3, ce = y1-y3, cf = y2-y3;
    float cg = z0-z3, ch = z1-z3, ci = z2-z3;

    // adjugate + det, uncontracted to mirror the reference
    float a00 = __fsub_rn(__fmul_rn(ce,ci), __fmul_rn(cf,ch));
    float a01 = __fsub_rn(__fmul_rn(cc,ch), __fmul_rn(cb,ci));
    float a02 = __fsub_rn(__fmul_rn(cb,cf), __fmul_rn(cc,ce));
    float a10 = __fsub_rn(__fmul_rn(cf,cg), __fmul_rn(cd,ci));
    float a11 = __fsub_rn(__fmul_rn(ca,ci), __fmul_rn(cc,cg));
    float a12 = __fsub_rn(__fmul_rn(cc,cd), __fmul_rn(ca,cf));
    float a20 = __fsub_rn(__fmul_rn(cd,ch), __fmul_rn(ce,cg));
    float a21 = __fsub_rn(__fmul_rn(cb,cg), __fmul_rn(ca,ch));
    float a22 = __fsub_rn(__fmul_rn(ca,ce), __fmul_rn(cb,cd));
    float u   = __fsub_rn(__fmul_rn(cd,ci), __fmul_rn(cf,cg));
    float det = __fadd_rn(__fsub_rn(__fmul_rn(ca,a00), __fmul_rn(cb,u)),
                          __fmul_rn(cc,a20));

    double inv = 1.0 / (double)det;
    float4 p0, p1, p2;
    p0.x = (float)((double)a00*inv); p0.y = (float)((double)a01*inv); p0.z = (float)((double)a02*inv);
    p1.x = (float)((double)a10*inv); p1.y = (float)((double)a11*inv); p1.z = (float)((double)a12*inv);
    p2.x = (float)((double)a20*inv); p2.y = (float)((double)a21*inv); p2.z = (float)((double)a22*inv);
    p0.w = (float)(-((double)a00*x3 + (double)a01*y3 + (double)a02*z3) * inv);
    p1.w = (float)(-((double)a10*x3 + (double)a11*y3 + (double)a12*z3) * inv);
    p2.w = (float)(-((double)a20*x3 + (double)a21*y3 + (double)a22*z3) * inv);

    // plane 3 (l3 = 1 - l0 - l1 - l2) linear-form coefficients (approx use only)
    float n3x = -(p0.x + p1.x + p2.x);
    float n3y = -(p0.y + p1.y + p2.y);
    float n3z = -(p0.z + p1.z + p2.z);
    float c3  = 1.0f - (p0.w + p1.w + p2.w);

    const float M = 1e-5f;  // conservative AABB margin
    float bxmin = fminf(fminf(x0,x1), fminf(x2,x3)) - M;
    float bxmax = fmaxf(fmaxf(x0,x1), fmaxf(x2,x3)) + M;
    float bymin = fminf(fminf(y0,y1), fminf(y2,y3)) - M;
    float bymax = fmaxf(fmaxf(y0,y1), fmaxf(y2,y3)) + M;
    float bzmin = fminf(fminf(z0,z1), fminf(z2,z3)) - M;
    float bzmax = fmaxf(fmaxf(z0,z1), fmaxf(z2,z3)) + M;

    Tet T;
    T.ib.x = max(0,  (int)ceilf ((96.f*bxmin + 95.f)*0.5f) - 1);
    T.ib.y = min(95, (int)floorf((96.f*bxmax + 95.f)*0.5f) + 1);
    T.ib.z = max(0,  (int)ceilf ((96.f*bymin + 95.f)*0.5f) - 1);
    T.ib.w = min(95, (int)floorf((96.f*bymax + 95.f)*0.5f) + 1);
    T.zb.x = max(0,  (int)ceilf ((96.f*bzmin + 95.f)*0.5f) - 1);
    T.zb.y = min(95, (int)floorf((96.f*bzmax + 95.f)*0.5f) + 1);

    int flags;
    if (!(fabsf(det) > 0.0f)) flags = 0;                 // degenerate -> never inside
    else if (ill_cond(p0.x,p0.y,p0.z,p0.w) || ill_cond(p1.x,p1.y,p1.z,p1.w) ||
             ill_cond(p2.x,p2.y,p2.z,p2.w) || ill_cond(n3x,n3y,n3z,c3))
        flags = 2;                                       // rare: exact chunked path
    else flags = 1;

    float4 w;
    w.x = (float)(-48.0 / (double)p0.z);
    w.y = (float)(-48.0 / (double)p1.z);
    w.z = (float)(-48.0 / (double)p2.z);
    w.w = (float)(-48.0 / (double)n3z);

    T.p0 = p0; T.p1 = p1; T.p2 = p2; T.w = w; T.flags = flags; T.pad = 0;
    g_t[t] = T;
}

// ---------------- 3) per-tet rasterize: exact z-run per column ------------
// block = one tet; 8 warps stride x rows; lanes = 32 y-columns per chunk.
__global__ __launch_bounds__(256) void vox_k(float* __restrict__ out) {
    __shared__ float s_p[G_];
    if (threadIdx.x < G_)
        s_p[threadIdx.x] = __fdiv_rn((float)(2*(int)threadIdx.x - 95), 96.0f);
    __syncthreads();

    const Tet& T = g_t[blockIdx.y * NF_ + blockIdx.x];
    int flags = T.flags;
    if (flags == 0) return;

    int warp = threadIdx.x >> 5, lane = threadIdx.x & 31;
    float4 P0 = T.p0, P1 = T.p1, P2 = T.p2;
    int4 ib = T.ib; int2 zb = T.zb;
    float* outb = out + (size_t)blockIdx.y * VOX_;

    if (flags == 2) {
        // -------- fallback: exact chunked test over whole box (R4 path) -----
        int nzc = ((zb.y - zb.x) >> 5) + 1;
        float pzc[3];
        #pragma unroll
        for (int k = 0; k < 3; ++k)
            pzc[k] = s_p[min(zb.x + k*32 + lane, 95)];
        for (int xi = ib.x; xi <= ib.y; ++xi) {
            float px  = s_p[xi];
            float e0x = fmaf(P0.x, px, P0.w);
            float e1x = fmaf(P1.x, px, P1.w);
            float e2x = fmaf(P2.x, px, P2.w);
            int rowx = xi * G_;
            for (int yi = ib.z + warp; yi <= ib.w; yi += 8) {
                float py = s_p[yi];
                float e0 = fmaf(P0.y, py, e0x);
                float e1 = fmaf(P1.y, py, e1x);
                float e2 = fmaf(P2.y, py, e2x);
                float* col = outb + (size_t)(rowx + yi) * G_ + zb.x + lane;
                #pragma unroll
                for (int k = 0; k < 3; ++k) {
                    if (k >= nzc) break;
                    float l0 = fmaf(P0.z, pzc[k], e0);
                    float l1 = fmaf(P1.z, pzc[k], e1);
                    float l2 = fmaf(P2.z, pzc[k], e2);
                    float l3 = 1.0f - (l0 + l1 + l2);
                    float m = fminf(fminf(l0, l1), fminf(l2, l3));
                    int z = zb.x + k*32 + lane;
                    if ((m >= 0.0f) && (z <= zb.y)) col[k*32] = 1.0f;
                }
            }
        }
        return;
    }

    // -------- fast path --------
    float4 W = T.w;
    bool s0 = P0.z > 0.0f, s1 = P1.z > 0.0f, s2 = P2.z > 0.0f;
    bool s3 = (-(P0.z + P1.z + P2.z)) > 0.0f;   // sign of n3z

    for (int xi = ib.x + warp; xi <= ib.y; xi += 8) {
        float px  = s_p[xi];
        float ex0 = fmaf(P0.x, px, P0.w);
        float ex1 = fmaf(P1.x, px, P1.w);
        float ex2 = fmaf(P2.x, px, P2.w);

        for (int ybase = ib.z; ybase <= ib.w; ybase += 32) {
            int  y   = ybase + lane;
            bool yok = (y <= ib.w);
            float py = s_p[y > 95 ? 95 : y];
            float e0 = fmaf(P0.y, py, ex0);
            float e1 = fmaf(P1.y, py, ex1);
            float e2 = fmaf(P2.y, py, ex2);
            float e3 = 1.0f - (e0 + e1 + e2);   // approx linear const, plane 3

            // approximate crossing positions in z-index space
            float i0 = fmaf(e0, W.x, 47.5f);
            float i1 = fmaf(e1, W.y, 47.5f);
            float i2 = fmaf(e2, W.z, 47.5f);
            float i3 = fmaf(e3, W.w, 47.5f);
            float lo = fmaxf(fmaxf(s0 ? i0 : -1e30f, s1 ? i1 : -1e30f),
                             fmaxf(s2 ? i2 : -1e30f, s3 ? i3 : -1e30f));
            float hi = fminf(fminf(s0 ? 1e30f : i0, s1 ? 1e30f : i1),
                             fminf(s2 ? 1e30f : i2, s3 ? 1e30f : i3));
            int sA = __float2int_ru(lo);
            int eA = __float2int_rd(hi);

            int st = 96, en = 0;                // empty encoding: st > en
            bool act = yok && (sA <= eA + 2);   // crossing err < 0.25 => safe skip
            if (__any_sync(0xffffffffu, act)) {
                // exact membership test — IDENTICAL FP chain to the passing kernel
                auto TST = [&](int z) -> bool {
                    float pz = s_p[z];
                    float l0 = fmaf(P0.z, pz, e0);
                    float l1 = fmaf(P1.z, pz, e1);
                    float l2 = fmaf(P2.z, pz, e2);
                    float l3 = 1.0f - (l0 + l1 + l2);
                    return fminf(fminf(l0, l1), fminf(l2, l3)) >= 0.0f;
                };
                if (act) {
                    int cs0 = min(max(sA-1, 0), 95);
                    int cs1 = min(max(sA  , 0), 95);
                    int cs2 = min(max(sA+1, 0), 95);
                    bool t0 = TST(cs0), t1 = TST(cs1), t2 = TST(cs2);
                    int stc = t0 ? cs0 : (t1 ? cs1 : (t2 ? cs2 : 96));
                    int ce0 = min(max(eA+1, 0), 95);
                    int ce1 = min(max(eA  , 0), 95);
                    int ce2 = min(max(eA-1, 0), 95);
                    bool u0 = TST(ce0), u1 = TST(ce1), u2 = TST(ce2);
                    int enc = u0 ? ce0 : (u1 ? ce1 : (u2 ? ce2 : -1));
                    if (stc <= enc) { st = stc; en = enc; }
                }
            }

            // phase 3: branch-free unrolled fill, lanes = z
            unsigned any = __ballot_sync(0xffffffffu, st <= en);
            if (any) {
                int pk = (st << 8) | en;        // st in [0,96], en in [0,95]
                float* base = outb + (size_t)(xi * G_ + ybase) * G_;
                bool wide = __any_sync(0xffffffffu, (en - st) >= 32);
                #pragma unroll
                for (int j = 0; j < 32; ++j) {
                    int pkj = __shfl_sync(0xffffffffu, pk, j);
                    int bs = pkj >> 8;
                    int be = pkj & 255;
                    int zz = bs + lane;
                    if (zz <= be) base[j * G_ + zz] = 1.0f;   // predicated STG
                }
                if (wide) {                      // rare: runs longer than 32
                    #pragma unroll 1
                    for (int j = 0; j < 32; ++j) {
                        int pkj = __shfl_sync(0xffffffffu, pk, j);
                        int bs = pkj >> 8;
                        int be = pkj & 255;
                        for (int zz = bs + 32 + lane; zz <= be; zz += 32)
                            base[j * G_ + zz] = 1.0f;
                    }
                }
            }
        }
    }
}

// ---------------- launch ----------------
extern "C" void kernel_launch(void* const* d_in, const int* in_sizes, int n_in,
                              void* d_out, int out_size) {
    const float* verts = (const float*)d_in[0];
    const void*  fac   = d_in[1];
    (void)in_sizes; (void)n_in; (void)out_size;

    zero_k  <<<(B_*VOX_/4) / 256, 256>>>((float4*)d_out);
    detect_k<<<1, 256>>>((const unsigned long long*)fac);
    prep_k  <<<(B_*NF_ + 255) / 256, 256>>>(verts, fac);
    vox_k   <<<dim3(NF_, B_), 256>>>((float*)d_out);
}

// round 11
// speedup vs baseline: 9.7224x; 1.1648x over previous
#include <cuda_runtime.h>

#define B_   8
#define NV_  2048
#define NF_  512
#define G_   96
#define VOX_ (G_*G_*G_)   // 884736

// ---------------- scratch (no allocation allowed) ----------------
struct Tet {
    float4 p0, p1, p2;   // plane r: (nx,ny,nz,c), lambda_r = nx*px+ny*py+nz*pz+c
    float4 w;            // per-plane -48/nz (x,y,z -> planes 0..2, w -> plane 3)
    int4   ib;           // xlo,xhi,ylo,yhi  (voxel index AABB, +1 guard)
    int2   zb;           // zlo,zhi
    int    flags;        // 0 = degenerate skip, 1 = fast path, 2 = fallback
    int    pad;
};
static __device__ Tet g_t[B_*NF_];
static __device__ int g_is32;

// ---------------- 0) output zero-fill ----------------
__global__ void zero_k(float4* __restrict__ o) {
    o[blockIdx.x * 256 + threadIdx.x] = make_float4(0.f, 0.f, 0.f, 0.f);
}

// ---------------- 1) facet dtype sniff (int64 vs silently-demoted int32) ---
__global__ void detect_k(const unsigned long long* __restrict__ f) {
    int any = 0;
    for (int idx = threadIdx.x; idx < B_*NF_*2; idx += blockDim.x)
        if (f[idx] >= (unsigned long long)NV_) any = 1;
    any = __syncthreads_or(any);
    if (threadIdx.x == 0) g_is32 = any;
}

// ---------------- 2) per-tet precompute ----------------
__device__ __forceinline__ bool ill_cond(float nx, float ny, float nz, float c) {
    float M = fmaxf(fmaxf(fabsf(nx), fabsf(ny)), fmaxf(fabsf(c), 1.0f));
    return 1e4f * fabsf(nz) < M;   // crossing-index error could exceed ~0.25 voxel
}

__global__ void prep_k(const float* __restrict__ verts, const void* __restrict__ fac) {
    int t = blockIdx.x * blockDim.x + threadIdx.x;
    if (t >= B_*NF_) return;
    int b = t >> 9;

    int i0, i1, i2, i3;
    if (g_is32) {
        const int* p = (const int*)fac + t*4;
        i0 = p[0]; i1 = p[1]; i2 = p[2]; i3 = p[3];
    } else {
        const long long* p = (const long long*)fac + t*4;
        i0 = (int)p[0]; i1 = (int)p[1]; i2 = (int)p[2]; i3 = (int)p[3];
    }

    const float* vb = verts + b * (NV_*3);
    float x0 = vb[3*i0+0], y0 = vb[3*i0+1], z0 = vb[3*i0+2];
    float x1 = vb[3*i1+0], y1 = vb[3*i1+1], z1 = vb[3*i1+2];
    float x2 = vb[3*i2+0], y2 = vb[3*i2+1], z2 = vb[3*i2+2];
    float x3 = vb[3*i3+0], y3 = vb[3*i3+1], z3 = vb[3*i3+2];

    float ca = x0-x3, cb = x1-x3, cc = x2-x3;
    float cd = y0-y3, ce = y1-y3, cf = y2-y3;
    float cg = z0-z3, ch = z1-z3, ci = z2-z3;

    // adjugate + det, uncontracted to mirror the reference
    float a00 = __fsub_rn(__fmul_rn(ce,ci), __fmul_rn(cf,ch));
    float a01 = __fsub_rn(__fmul_rn(cc,ch), __fmul_rn(cb,ci));
    float a02 = __fsub_rn(__fmul_rn(cb,cf), __fmul_rn(cc,ce));
    float a10 = __fsub_rn(__fmul_rn(cf,cg), __fmul_rn(cd,ci));
    float a11 = __fsub_rn(__fmul_rn(ca,ci), __fmul_rn(cc,cg));
    float a12 = __fsub_rn(__fmul_rn(cc,cd), __fmul_rn(ca,cf));
    float a20 = __fsub_rn(__fmul_rn(cd,ch), __fmul_rn(ce,cg));
    float a21 = __fsub_rn(__fmul_rn(cb,cg), __fmul_rn(ca,ch));
    float a22 = __fsub_rn(__fmul_rn(ca,ce), __fmul_rn(cb,cd));
    float u   = __fsub_rn(__fmul_rn(cd,ci), __fmul_rn(cf,cg));
    float det = __fadd_rn(__fsub_rn(__fmul_rn(ca,a00), __fmul_rn(cb,u)),
                          __fmul_rn(cc,a20));

    double inv = 1.0 / (double)det;
    float4 p0, p1, p2;
    p0.x = (float)((double)a00*inv); p0.y = (float)((double)a01*inv); p0.z = (float)((double)a02*inv);
    p1.x = (float)((double)a10*inv); p1.y = (float)((double)a11*inv); p1.z = (float)((double)a12*inv);
    p2.x = (float)((double)a20*inv); p2.y = (float)((double)a21*inv); p2.z = (float)((double)a22*inv);
    p0.w = (float)(-((double)a00*x3 + (double)a01*y3 + (double)a02*z3) * inv);
    p1.w = (float)(-((double)a10*x3 + (double)a11*y3 + (double)a12*z3) * inv);
    p2.w = (float)(-((double)a20*x3 + (double)a21*y3 + (double)a22*z3) * inv);

    // plane 3 (l3 = 1 - l0 - l1 - l2) linear-form coefficients (approx use only)
    float n3x = -(p0.x + p1.x + p2.x);
    float n3y = -(p0.y + p1.y + p2.y);
    float n3z = -(p0.z + p1.z + p2.z);
    float c3  = 1.0f - (p0.w + p1.w + p2.w);

    const float M = 1e-5f;  // conservative AABB margin
    float bxmin = fminf(fminf(x0,x1), fminf(x2,x3)) - M;
    float bxmax = fmaxf(fmaxf(x0,x1), fmaxf(x2,x3)) + M;
    float bymin = fminf(fminf(y0,y1), fminf(y2,y3)) - M;
    float bymax = fmaxf(fmaxf(y0,y1), fmaxf(y2,y3)) + M;
    float bzmin = fminf(fminf(z0,z1), fminf(z2,z3)) - M;
    float bzmax = fmaxf(fmaxf(z0,z1), fmaxf(z2,z3)) + M;

    Tet T;
    T.ib.x = max(0,  (int)ceilf ((96.f*bxmin + 95.f)*0.5f) - 1);
    T.ib.y = min(95, (int)floorf((96.f*bxmax + 95.f)*0.5f) + 1);
    T.ib.z = max(0,  (int)ceilf ((96.f*bymin + 95.f)*0.5f) - 1);
    T.ib.w = min(95, (int)floorf((96.f*bymax + 95.f)*0.5f) + 1);
    T.zb.x = max(0,  (int)ceilf ((96.f*bzmin + 95.f)*0.5f) - 1);
    T.zb.y = min(95, (int)floorf((96.f*bzmax + 95.f)*0.5f) + 1);

    int flags;
    if (!(fabsf(det) > 0.0f)) flags = 0;                 // degenerate -> never inside
    else if (ill_cond(p0.x,p0.y,p0.z,p0.w) || ill_cond(p1.x,p1.y,p1.z,p1.w) ||
             ill_cond(p2.x,p2.y,p2.z,p2.w) || ill_cond(n3x,n3y,n3z,c3))
        flags = 2;                                       // rare: exact chunked path
    else flags = 1;

    float4 w;
    w.x = (float)(-48.0 / (double)p0.z);
    w.y = (float)(-48.0 / (double)p1.z);
    w.z = (float)(-48.0 / (double)p2.z);
    w.w = (float)(-48.0 / (double)n3z);

    T.p0 = p0; T.p1 = p1; T.p2 = p2; T.w = w; T.flags = flags; T.pad = 0;
    g_t[t] = T;
}

// ---------------- 3) per-tet rasterize: exact z-run per column ------------
// block = one tet; 8 warps stride x rows; lanes = 32 y-columns per chunk.
__global__ __launch_bounds__(256) void vox_k(float* __restrict__ out) {
    __shared__ float s_p[G_];
    if (threadIdx.x < G_)
        s_p[threadIdx.x] = __fdiv_rn((float)(2*(int)threadIdx.x - 95), 96.0f);
    __syncthreads();

    const Tet& T = g_t[blockIdx.y * NF_ + blockIdx.x];
    int flags = T.flags;
    if (flags == 0) return;

    int warp = threadIdx.x >> 5, lane = threadIdx.x & 31;
    float4 P0 = T.p0, P1 = T.p1, P2 = T.p2;
    int4 ib = T.ib; int2 zb = T.zb;
    float* outb = out + (size_t)blockIdx.y * VOX_;

    if (flags == 2) {
        // -------- fallback: exact chunked test over whole box (R4 path) -----
        int nzc = ((zb.y - zb.x) >> 5) + 1;
        float pzc[3];
        #pragma unroll
        for (int k = 0; k < 3; ++k)
            pzc[k] = s_p[min(zb.x + k*32 + lane, 95)];
        for (int xi = ib.x; xi <= ib.y; ++xi) {
            float px  = s_p[xi];
            float e0x = fmaf(P0.x, px, P0.w);
            float e1x = fmaf(P1.x, px, P1.w);
            float e2x = fmaf(P2.x, px, P2.w);
            int rowx = xi * G_;
            for (int yi = ib.z + warp; yi <= ib.w; yi += 8) {
                float py = s_p[yi];
                float e0 = fmaf(P0.y, py, e0x);
                float e1 = fmaf(P1.y, py, e1x);
                float e2 = fmaf(P2.y, py, e2x);
                float* col = outb + (size_t)(rowx + yi) * G_ + zb.x + lane;
                #pragma unroll
                for (int k = 0; k < 3; ++k) {
                    if (k >= nzc) break;
                    float l0 = fmaf(P0.z, pzc[k], e0);
                    float l1 = fmaf(P1.z, pzc[k], e1);
                    float l2 = fmaf(P2.z, pzc[k], e2);
                    float l3 = 1.0f - (l0 + l1 + l2);
                    float m = fminf(fminf(l0, l1), fminf(l2, l3));
                    int z = zb.x + k*32 + lane;
                    if ((m >= 0.0f) && (z <= zb.y)) col[k*32] = 1.0f;
                }
            }
        }
        return;
    }

    // -------- fast path --------
    float4 W = T.w;
    bool s0 = P0.z > 0.0f, s1 = P1.z > 0.0f, s2 = P2.z > 0.0f;
    bool s3 = (-(P0.z + P1.z + P2.z)) > 0.0f;   // sign of n3z

    for (int xi = ib.x + warp; xi <= ib.y; xi += 8) {
        float px  = s_p[xi];
        float ex0 = fmaf(P0.x, px, P0.w);
        float ex1 = fmaf(P1.x, px, P1.w);
        float ex2 = fmaf(P2.x, px, P2.w);

        for (int ybase = ib.z; ybase <= ib.w; ybase += 32) {
            int  y   = ybase + lane;
            bool yok = (y <= ib.w);
            float py = s_p[y > 95 ? 95 : y];
            float e0 = fmaf(P0.y, py, ex0);
            float e1 = fmaf(P1.y, py, ex1);
            float e2 = fmaf(P2.y, py, ex2);
            float e3 = 1.0f - (e0 + e1 + e2);   // approx linear const, plane 3

            // approximate crossing positions in z-index space
            float i0 = fmaf(e0, W.x, 47.5f);
            float i1 = fmaf(e1, W.y, 47.5f);
            float i2 = fmaf(e2, W.z, 47.5f);
            float i3 = fmaf(e3, W.w, 47.5f);
            float lo = fmaxf(fmaxf(s0 ? i0 : -1e30f, s1 ? i1 : -1e30f),
                             fmaxf(s2 ? i2 : -1e30f, s3 ? i3 : -1e30f));
            float hi = fminf(fminf(s0 ? 1e30f : i0, s1 ? 1e30f : i1),
                             fminf(s2 ? 1e30f : i2, s3 ? 1e30f : i3));
            int sA = __float2int_ru(lo);
            int eA = __float2int_rd(hi);

            int st = 96, en = 0;                // empty encoding: st > en
            bool act = yok && (sA <= eA + 2);   // crossing err < 0.25 => safe skip
            if (__any_sync(0xffffffffu, act)) {
                // exact membership test — IDENTICAL FP chain to the passing kernel
                auto TST = [&](int z) -> bool {
                    float pz = s_p[z];
                    float l0 = fmaf(P0.z, pz, e0);
                    float l1 = fmaf(P1.z, pz, e1);
                    float l2 = fmaf(P2.z, pz, e2);
                    float l3 = 1.0f - (l0 + l1 + l2);
                    return fminf(fminf(l0, l1), fminf(l2, l3)) >= 0.0f;
                };
                if (act) {
                    int cs0 = min(max(sA-1, 0), 95);
                    int cs1 = min(max(sA  , 0), 95);
                    int cs2 = min(max(sA+1, 0), 95);
                    bool t0 = TST(cs0), t1 = TST(cs1), t2 = TST(cs2);
                    int stc = t0 ? cs0 : (t1 ? cs1 : (t2 ? cs2 : 96));
                    int ce0 = min(max(eA+1, 0), 95);
                    int ce1 = min(max(eA  , 0), 95);
                    int ce2 = min(max(eA-1, 0), 95);
                    bool u0 = TST(ce0), u1 = TST(ce1), u2 = TST(ce2);
                    int enc = u0 ? ce0 : (u1 ? ce1 : (u2 ? ce2 : -1));
                    if (stc <= enc) { st = stc; en = enc; }
                }
            }

            // ---- phase 3: up to 3 flat predicated passes (z offsets 0/32/64)
            int len = en - st;                           // < 0 when empty
            unsigned m1 = __ballot_sync(0xffffffffu, len >= 0);
            if (m1) {
                int pk = (st << 8) | en;                 // st in [0,96], en in [0,95]
                float* base = outb + (size_t)(xi * G_ + ybase) * G_;
                unsigned m2 = __ballot_sync(0xffffffffu, len >= 32);
                unsigned m3 = __ballot_sync(0xffffffffu, len >= 64);

                int j1 = 31 - __clz(m1);                 // highest nonempty column
                #pragma unroll
                for (int j = 0; j < 32; ++j) {
                    if (j > j1) break;                   // warp-uniform break
                    int pkj = __shfl_sync(0xffffffffu, pk, j);
                    int bs = pkj >> 8, be = pkj & 255;
                    int zz = bs + lane;
                    if (zz <= be) base[j * G_ + zz] = 1.0f;
                }
                if (m2) {
                    int j2 = 31 - __clz(m2);
                    #pragma unroll
                    for (int j = 0; j < 32; ++j) {
                        if (j > j2) break;
                        int pkj = __shfl_sync(0xffffffffu, pk, j);
                        int bs = pkj >> 8, be = pkj & 255;
                        int zz = bs + 32 + lane;
                        if (zz <= be) base[j * G_ + zz] = 1.0f;
                    }
                }
                if (m3) {                                // len <= 95, so 3 passes cover all
                    int j3 = 31 - __clz(m3);
                    #pragma unroll
                    for (int j = 0; j < 32; ++j) {
                        if (j > j3) break;
                        int pkj = __shfl_sync(0xffffffffu, pk, j);
                        int bs = pkj >> 8, be = pkj & 255;
                        int zz = bs + 64 + lane;
                        if (zz <= be) base[j * G_ + zz] = 1.0f;
                    }
                }
            }
        }
    }
}

// ---------------- launch ----------------
extern "C" void kernel_launch(void* const* d_in, const int* in_sizes, int n_in,
                              void* d_out, int out_size) {
    const float* verts = (const float*)d_in[0];
    const void*  fac   = d_in[1];
    (void)in_sizes; (void)n_in; (void)out_size;

    zero_k  <<<(B_*VOX_/4) / 256, 256>>>((float4*)d_out);
    detect_k<<<1, 256>>>((const unsigned long long*)fac);
    prep_k  <<<(B_*NF_ + 255) / 256, 256>>>(verts, fac);
    vox_k   <<<dim3(NF_, B_), 256>>>((float*)d_out);
}